// round 1
// baseline (speedup 1.0000x reference)
#include <cuda_runtime.h>

#define NN 100000
#define NE 1600000
#define HP 20          // padded node feature width (19 used, [19]=0)

// ---------------- device scratch (static; no allocations) ----------------
__device__ __align__(16) float  g_h[NN * HP];     // node state [N,20]
__device__ float4 g_A[NN * 4];                    // h @ eW1_top + eb1
__device__ float4 g_B[NN * 4];                    // h @ eW1_bot
__device__ float4 g_C[NN * 4];                    // h @ msgW1_bot (node/out)
__device__ float4 g_macc[NN * 4];                 // aggregated projected msgs
__device__ int    g_deg[NN];
__device__ int    g_rowptr[NN + 1];
__device__ int    g_wofs[NN];
__device__ __align__(16) int2  g_se[NE];          // sorted (start,end)
__device__ __align__(16) float g_gate[NE];

__device__ __forceinline__ void fma4(float4& a, float s, float4 w) {
    a.x += s * w.x; a.y += s * w.y; a.z += s * w.z; a.w += s * w.w;
}
__device__ __forceinline__ float fsig(float z) {   // z >= 0 at call sites
    return __fdividef(1.f, 1.f + __expf(-z));
}

// ---------------- counting sort: build CSR by 'start' ----------------
__global__ void k_zero_deg() {
    int i = blockIdx.x * blockDim.x + threadIdx.x;
    if (i < NN) g_deg[i] = 0;
}
__global__ void k_hist(const int* __restrict__ start) {
    int e = blockIdx.x * blockDim.x + threadIdx.x;
    if (e < NE) atomicAdd(&g_deg[start[e]], 1);
}
__global__ void k_scan() {
    __shared__ int ssum[1024];
    int t = threadIdx.x;
    const int CH = (NN + 1023) / 1024;   // 98
    int lo = t * CH, hi = min(lo + CH, NN);
    int s = 0;
    for (int j = lo; j < hi; j++) s += g_deg[j];
    ssum[t] = s;
    __syncthreads();
    for (int off = 1; off < 1024; off <<= 1) {
        int v = (t >= off) ? ssum[t - off] : 0;
        __syncthreads();
        ssum[t] += v;
        __syncthreads();
    }
    int run = (t == 0) ? 0 : ssum[t - 1];
    for (int j = lo; j < hi; j++) {
        g_rowptr[j] = run;
        g_wofs[j]   = run;
        run += g_deg[j];
    }
    if (t == 1023) g_rowptr[NN] = NE;
}
__global__ void k_scatter(const int* __restrict__ ei) {
    int e = blockIdx.x * blockDim.x + threadIdx.x;
    if (e < NE) {
        int s = ei[e], t = ei[NE + e];
        int pos = atomicAdd(&g_wofs[s], 1);
        g_se[pos] = make_int2(s, t);
    }
}

// ---------------- encoder: h = [x@encW + encb, x, 0] ----------------
__global__ void k_encode(const float* __restrict__ x,
                         const float* __restrict__ W,
                         const float* __restrict__ b) {
    int n = blockIdx.x * blockDim.x + threadIdx.x;
    if (n >= NN) return;
    float x0 = x[3 * n], x1 = x[3 * n + 1], x2 = x[3 * n + 2];
    float* hr = g_h + n * HP;
    #pragma unroll
    for (int j = 0; j < 16; j++)
        hr[j] = b[j] + x0 * W[j] + x1 * W[16 + j] + x2 * W[32 + j];
    hr[16] = x0; hr[17] = x1; hr[18] = x2; hr[19] = 0.f;
}

// ---------------- per-node precompute: A, B, C ----------------
__global__ void __launch_bounds__(256) k_pre(const float* __restrict__ eW1,
                                             const float* __restrict__ eb1,
                                             const float* __restrict__ cW) {
    __shared__ float4 sW1[152];  // full eW1 [38,16]
    __shared__ float4 sCW[76];   // msg W1 bottom [19,16]
    __shared__ float4 sb1[4];
    int tid = threadIdx.x;
    for (int i = tid; i < 152; i += blockDim.x) sW1[i] = ((const float4*)eW1)[i];
    for (int i = tid; i < 76;  i += blockDim.x) sCW[i] = ((const float4*)cW)[i];
    if (tid < 4) sb1[tid] = ((const float4*)eb1)[tid];
    __syncthreads();

    int n = blockIdx.x * blockDim.x + tid;
    if (n >= NN) return;
    float hr[20];
    const float4* h4 = (const float4*)g_h + n * 5;
    #pragma unroll
    for (int r = 0; r < 5; r++) {
        float4 v = h4[r];
        hr[4*r] = v.x; hr[4*r+1] = v.y; hr[4*r+2] = v.z; hr[4*r+3] = v.w;
    }
    float4 a[4], bb[4], c[4];
    #pragma unroll
    for (int r = 0; r < 4; r++) {
        a[r]  = sb1[r];
        bb[r] = make_float4(0.f, 0.f, 0.f, 0.f);
        c[r]  = make_float4(0.f, 0.f, 0.f, 0.f);
    }
    #pragma unroll
    for (int k = 0; k < 19; k++) {
        float hk = hr[k];
        #pragma unroll
        for (int r = 0; r < 4; r++) {
            fma4(a[r],  hk, sW1[k * 4 + r]);
            fma4(bb[r], hk, sW1[(19 + k) * 4 + r]);
            fma4(c[r],  hk, sCW[k * 4 + r]);
        }
    }
    #pragma unroll
    for (int r = 0; r < 4; r++) {
        g_A[n * 4 + r] = a[r];
        g_B[n * 4 + r] = bb[r];
        g_C[n * 4 + r] = c[r];
    }
}

// ---------------- edge kernel: gate[e] = sigmoid(relu(MLP)) , EPT=2 ----------------
__global__ void __launch_bounds__(256) k_edge(const float* __restrict__ W2,
                                              const float* __restrict__ b2,
                                              const float* __restrict__ W3,
                                              const float* __restrict__ b3) {
    __shared__ float4 sW2[64], sb2[4], sW3[4];
    __shared__ float  sb3;
    int tid = threadIdx.x;
    if (tid < 64) sW2[tid] = ((const float4*)W2)[tid];
    else if (tid < 68) sb2[tid - 64] = ((const float4*)b2)[tid - 64];
    else if (tid < 72) sW3[tid - 68] = ((const float4*)W3)[tid - 68];
    else if (tid == 72) sb3 = b3[0];
    __syncthreads();

    int g = blockIdx.x * blockDim.x + tid;   // pair index
    if (g >= NE / 2) return;
    int4 p = ((const int4*)g_se)[g];
    int s0 = p.x, t0 = p.y, s1 = p.z, t1 = p.w;

    float h1a[16], h1b[16];
    #pragma unroll
    for (int r = 0; r < 4; r++) {
        float4 av = g_A[s0 * 4 + r], bv = g_B[t0 * 4 + r];
        h1a[4*r]   = fmaxf(av.x + bv.x, 0.f);
        h1a[4*r+1] = fmaxf(av.y + bv.y, 0.f);
        h1a[4*r+2] = fmaxf(av.z + bv.z, 0.f);
        h1a[4*r+3] = fmaxf(av.w + bv.w, 0.f);
        float4 aw = g_A[s1 * 4 + r], bw = g_B[t1 * 4 + r];
        h1b[4*r]   = fmaxf(aw.x + bw.x, 0.f);
        h1b[4*r+1] = fmaxf(aw.y + bw.y, 0.f);
        h1b[4*r+2] = fmaxf(aw.z + bw.z, 0.f);
        h1b[4*r+3] = fmaxf(aw.w + bw.w, 0.f);
    }
    float h2a[16], h2b[16];
    #pragma unroll
    for (int r = 0; r < 4; r++) {
        float4 bv = sb2[r];
        h2a[4*r] = bv.x; h2a[4*r+1] = bv.y; h2a[4*r+2] = bv.z; h2a[4*r+3] = bv.w;
        h2b[4*r] = bv.x; h2b[4*r+1] = bv.y; h2b[4*r+2] = bv.z; h2b[4*r+3] = bv.w;
    }
    #pragma unroll
    for (int k = 0; k < 16; k++) {
        float xa = h1a[k], xb = h1b[k];
        #pragma unroll
        for (int r = 0; r < 4; r++) {
            float4 w = sW2[k * 4 + r];
            h2a[4*r]   += xa * w.x;  h2b[4*r]   += xb * w.x;
            h2a[4*r+1] += xa * w.y;  h2b[4*r+1] += xb * w.y;
            h2a[4*r+2] += xa * w.z;  h2b[4*r+2] += xb * w.z;
            h2a[4*r+3] += xa * w.w;  h2b[4*r+3] += xb * w.w;
        }
    }
    float za = sb3, zb = sb3;
    #pragma unroll
    for (int r = 0; r < 4; r++) {
        float4 w = sW3[r];
        za += fmaxf(h2a[4*r],   0.f) * w.x + fmaxf(h2a[4*r+1], 0.f) * w.y
            + fmaxf(h2a[4*r+2], 0.f) * w.z + fmaxf(h2a[4*r+3], 0.f) * w.w;
        zb += fmaxf(h2b[4*r],   0.f) * w.x + fmaxf(h2b[4*r+1], 0.f) * w.y
            + fmaxf(h2b[4*r+2], 0.f) * w.z + fmaxf(h2b[4*r+3], 0.f) * w.w;
    }
    float ga = fsig(fmaxf(za, 0.f));
    float gb = fsig(fmaxf(zb, 0.f));
    ((float2*)g_gate)[g] = make_float2(ga, gb);
}

// ---------------- aggregation: macc[s] = sum gate * C[end]  (CSR, no atomics) ----------------
__global__ void k_agg() {
    int tid = blockIdx.x * blockDim.x + threadIdx.x;
    if (tid >= NN * 4) return;
    int n = tid >> 2, q = tid & 3;
    int lo = g_rowptr[n], hi = g_rowptr[n + 1];
    float4 acc = make_float4(0.f, 0.f, 0.f, 0.f);
    for (int j = lo; j < hi; j++) {
        int t = g_se[j].y;
        float gt = g_gate[j];
        fma4(acc, gt, g_C[t * 4 + q]);
    }
    g_macc[n * 4 + q] = acc;
}

// ---------------- node update (node nets / final out net) ----------------
__global__ void __launch_bounds__(256) k_post(const float* __restrict__ W1,
                                              const float* __restrict__ b1,
                                              const float* __restrict__ W2,
                                              const float* __restrict__ b2,
                                              const float* __restrict__ W3,
                                              const float* __restrict__ b3,
                                              const float* __restrict__ x,
                                              float* __restrict__ out,
                                              int last) {
    __shared__ float4 sW1[76], sW2v[64], sW3v[64], sb1[4], sb2v[4], sb3arr[4];
    __shared__ float  sb3s;
    int tid = threadIdx.x;
    for (int i = tid; i < 76; i += blockDim.x) sW1[i]  = ((const float4*)W1)[i];
    for (int i = tid; i < 64; i += blockDim.x) sW2v[i] = ((const float4*)W2)[i];
    int nW3 = last ? 4 : 64;
    for (int i = tid; i < nW3; i += blockDim.x) sW3v[i] = ((const float4*)W3)[i];
    if (tid < 4) sb1[tid] = ((const float4*)b1)[tid];
    else if (tid < 8) sb2v[tid - 4] = ((const float4*)b2)[tid - 4];
    else if (tid < 12) {
        if (!last) sb3arr[tid - 8] = ((const float4*)b3)[tid - 8];
        else if (tid == 8) sb3s = b3[0];
    }
    __syncthreads();

    int n = blockIdx.x * blockDim.x + tid;
    if (n >= NN) return;
    float hr[20];
    const float4* h4 = (const float4*)g_h + n * 5;
    #pragma unroll
    for (int r = 0; r < 5; r++) {
        float4 v = h4[r];
        hr[4*r] = v.x; hr[4*r+1] = v.y; hr[4*r+2] = v.z; hr[4*r+3] = v.w;
    }
    // layer1: relu(h@W1_top + macc + b1)   (macc already holds msgs@W1_bot)
    float4 l1v[4];
    #pragma unroll
    for (int r = 0; r < 4; r++) {
        float4 m = g_macc[n * 4 + r], bv = sb1[r];
        l1v[r] = make_float4(m.x + bv.x, m.y + bv.y, m.z + bv.z, m.w + bv.w);
    }
    #pragma unroll
    for (int k = 0; k < 19; k++) {
        float hk = hr[k];
        #pragma unroll
        for (int r = 0; r < 4; r++) fma4(l1v[r], hk, sW1[k * 4 + r]);
    }
    float l1[16];
    #pragma unroll
    for (int r = 0; r < 4; r++) {
        l1[4*r]   = fmaxf(l1v[r].x, 0.f);
        l1[4*r+1] = fmaxf(l1v[r].y, 0.f);
        l1[4*r+2] = fmaxf(l1v[r].z, 0.f);
        l1[4*r+3] = fmaxf(l1v[r].w, 0.f);
    }
    // layer2
    float4 l2v[4];
    #pragma unroll
    for (int r = 0; r < 4; r++) l2v[r] = sb2v[r];
    #pragma unroll
    for (int k = 0; k < 16; k++) {
        float xk = l1[k];
        #pragma unroll
        for (int r = 0; r < 4; r++) fma4(l2v[r], xk, sW2v[k * 4 + r]);
    }
    float l2[16];
    #pragma unroll
    for (int r = 0; r < 4; r++) {
        l2[4*r]   = fmaxf(l2v[r].x, 0.f);
        l2[4*r+1] = fmaxf(l2v[r].y, 0.f);
        l2[4*r+2] = fmaxf(l2v[r].z, 0.f);
        l2[4*r+3] = fmaxf(l2v[r].w, 0.f);
    }
    if (last) {
        float z = sb3s;
        #pragma unroll
        for (int r = 0; r < 4; r++) {
            float4 w = sW3v[r];
            z += l2[4*r] * w.x + l2[4*r+1] * w.y + l2[4*r+2] * w.z + l2[4*r+3] * w.w;
        }
        out[n] = __fdividef(1.f, 1.f + __expf(-z));
    } else {
        float4 l3v[4];
        #pragma unroll
        for (int r = 0; r < 4; r++) l3v[r] = sb3arr[r];
        #pragma unroll
        for (int k = 0; k < 16; k++) {
            float xk = l2[k];
            #pragma unroll
            for (int r = 0; r < 4; r++) fma4(l3v[r], xk, sW3v[k * 4 + r]);
        }
        // new h = concat(relu(l3), x) + h_old   (pad slot [19] stays 0)
        float4* hw = (float4*)(g_h + n * HP);
        #pragma unroll
        for (int r = 0; r < 4; r++) {
            float4 v;
            v.x = fmaxf(l3v[r].x, 0.f) + hr[4*r];
            v.y = fmaxf(l3v[r].y, 0.f) + hr[4*r+1];
            v.z = fmaxf(l3v[r].z, 0.f) + hr[4*r+2];
            v.w = fmaxf(l3v[r].w, 0.f) + hr[4*r+3];
            hw[r] = v;
        }
        float* hs = g_h + n * HP;
        hs[16] = x[3*n]     + hr[16];
        hs[17] = x[3*n + 1] + hr[17];
        hs[18] = x[3*n + 2] + hr[18];
    }
}

// ---------------- launch ----------------
extern "C" void kernel_launch(void* const* d_in, const int* in_sizes, int n_in,
                              void* d_out, int out_size) {
    const float* x    = (const float*)d_in[0];
    const int*   ei   = (const int*)  d_in[1];
    const float* encW = (const float*)d_in[2];
    const float* encb = (const float*)d_in[3];
    const float* eW1  = (const float*)d_in[4];
    const float* eb1  = (const float*)d_in[5];
    const float* eW2  = (const float*)d_in[6];
    const float* eb2  = (const float*)d_in[7];
    const float* eW3  = (const float*)d_in[8];
    const float* eb3  = (const float*)d_in[9];
    const float* nW1  = (const float*)d_in[10];
    const float* nb1  = (const float*)d_in[11];
    const float* nW2  = (const float*)d_in[12];
    const float* nb2  = (const float*)d_in[13];
    const float* nW3  = (const float*)d_in[14];
    const float* nb3  = (const float*)d_in[15];
    const float* oW1  = (const float*)d_in[16];
    const float* ob1  = (const float*)d_in[17];
    const float* oW2  = (const float*)d_in[18];
    const float* ob2  = (const float*)d_in[19];
    const float* oW3  = (const float*)d_in[20];
    const float* ob3  = (const float*)d_in[21];
    float* out = (float*)d_out;

    const int B = 256;
    k_zero_deg<<<(NN + B - 1) / B, B>>>();
    k_hist   <<<(NE + B - 1) / B, B>>>(ei);
    k_scan   <<<1, 1024>>>();
    k_scatter<<<(NE + B - 1) / B, B>>>(ei);
    k_encode <<<(NN + B - 1) / B, B>>>(x, encW, encb);

    for (int i = 0; i < 3; i++) {
        const float* cW = ((i < 2) ? (nW1 + i * 608) : oW1) + 19 * 16;
        k_pre <<<(NN + B - 1) / B, B>>>(eW1 + i * 608, eb1 + i * 16, cW);
        k_edge<<<(NE / 2 + B - 1) / B, B>>>(eW2 + i * 256, eb2 + i * 16,
                                            eW3 + i * 16, eb3 + i);
        k_agg <<<(NN * 4 + B - 1) / B, B>>>();
        if (i < 2)
            k_post<<<(NN + B - 1) / B, B>>>(nW1 + i * 608, nb1 + i * 16,
                                            nW2 + i * 256, nb2 + i * 16,
                                            nW3 + i * 256, nb3 + i * 16,
                                            x, out, 0);
        else
            k_post<<<(NN + B - 1) / B, B>>>(oW1, ob1, oW2, ob2, oW3, ob3,
                                            x, out, 1);
    }
}